// round 2
// baseline (speedup 1.0000x reference)
#include <cuda_runtime.h>

#define NN 128
#define LFULL 1024
#define CC 512
#define KTOT 2045
#define L1S 1023
#define L2S 1022

static __device__ __constant__ float INV_T = 14.2857142857142857f; // 1/0.07

// Scratch (device globals — allocation-free rule)
__device__ float g_U[(size_t)NN * L1S * CC];     // 268 MB: U = T @ W, rows (n,l)
__device__ float g_tb[L1S * NN];                 // tb[l][n] = t[n,l+s] . b
__device__ float g_tmp[(size_t)L1S * NN * NN];   // 67 MB: Gram tiles [l][n][m]
__device__ unsigned int g_cnt[2];                // accuracy counters

__global__ void init_kernel() { g_cnt[0] = 0u; g_cnt[1] = 0u; }

// tb[l][n] = dot(timesteps[n, l+step, :], b)
__global__ void tb_kernel(const float* __restrict__ t, const float* __restrict__ b,
                          int Lp, int step) {
    int l = blockIdx.x, n = threadIdx.x;
    const float4* r4 = (const float4*)(t + ((size_t)n * LFULL + l + step) * CC);
    const float4* b4 = (const float4*)b;
    float s = 0.f;
#pragma unroll 8
    for (int i = 0; i < CC / 4; i++) {
        float4 a = r4[i], bb = b4[i];
        s += a.x * bb.x + a.y * bb.y + a.z * bb.z + a.w * bb.w;
    }
    g_tb[l * NN + n] = s;
}

// U[r, p] = sum_c T_row(r)[c] * W[c, p]; r = n*Lp + l, T row = timesteps[n, l+step, :]
// Tiles: 128x128x8, 256 threads, 8x8 per thread.
__global__ __launch_bounds__(256, 2)
void gemmU_kernel(const float* __restrict__ T, const float* __restrict__ W,
                  int Lp, int step) {
    __shared__ float As[8][128];
    __shared__ float Bs[8][128];
    __shared__ unsigned rowbase[128];
    int tid = threadIdx.x;
    int r0 = blockIdx.y * 128;
    if (tid < 128) {
        int r = r0 + tid;
        int n = r / Lp;
        int l = r - n * Lp;
        rowbase[tid] = (unsigned)((n * LFULL + l + step) * CC);
    }
    __syncthreads();
    int colbase = blockIdx.x * 128;
    int arow = tid >> 1, acol = (tid & 1) * 4;
    int brow = tid >> 5, bcol = (tid & 31) * 4;
    int tx = tid & 15, ty = tid >> 4;
    float acc[8][8] = {};
    for (int kt = 0; kt < CC; kt += 8) {
        float4 a = *(const float4*)(T + rowbase[arow] + kt + acol);
        float4 b = *(const float4*)(W + (size_t)(kt + brow) * CC + colbase + bcol);
        __syncthreads();
        As[acol + 0][arow] = a.x; As[acol + 1][arow] = a.y;
        As[acol + 2][arow] = a.z; As[acol + 3][arow] = a.w;
        *(float4*)&Bs[brow][bcol] = b;
        __syncthreads();
#pragma unroll
        for (int kk = 0; kk < 8; kk++) {
            float ar[8], br[8];
            *(float4*)(ar)     = *(const float4*)&As[kk][ty * 8];
            *(float4*)(ar + 4) = *(const float4*)&As[kk][ty * 8 + 4];
            *(float4*)(br)     = *(const float4*)&Bs[kk][tx * 8];
            *(float4*)(br + 4) = *(const float4*)&Bs[kk][tx * 8 + 4];
#pragma unroll
            for (int i = 0; i < 8; i++)
#pragma unroll
                for (int j = 0; j < 8; j++)
                    acc[i][j] = fmaf(ar[i], br[j], acc[i][j]);
        }
    }
#pragma unroll
    for (int i = 0; i < 8; i++) {
        size_t base = (size_t)(r0 + ty * 8 + i) * CC + colbase + tx * 8;
        *(float4*)&g_U[base]     = make_float4(acc[i][0], acc[i][1], acc[i][2], acc[i][3]);
        *(float4*)&g_U[base + 4] = make_float4(acc[i][4], acc[i][5], acc[i][6], acc[i][7]);
    }
}

// Per-l Gram: G[n,m] = sum_k U[n,l,k] * P[m,l,k] (+ tb[n]); also NCE accuracy count.
__global__ __launch_bounds__(256, 2)
void gemmL_kernel(const float* __restrict__ P, int Lp, int stepIdx) {
    int l = blockIdx.x;
    __shared__ float As[8][128];
    __shared__ float Bs[8][128];
    __shared__ float pos[128];
    __shared__ unsigned char flg[128][16];
    int tid = threadIdx.x;
    int row = tid >> 1, koff = (tid & 1) * 4;
    int tx = tid & 15, ty = tid >> 4;
    const float* ubase = g_U + ((size_t)row * Lp + l) * CC + koff;
    const float* pbase = P + ((size_t)row * LFULL + l) * CC + koff;
    float acc[8][8] = {};
    for (int kt = 0; kt < CC; kt += 8) {
        float4 a = *(const float4*)(ubase + kt);
        float4 b = *(const float4*)(pbase + kt);
        __syncthreads();
        As[koff + 0][row] = a.x; As[koff + 1][row] = a.y;
        As[koff + 2][row] = a.z; As[koff + 3][row] = a.w;
        Bs[koff + 0][row] = b.x; Bs[koff + 1][row] = b.y;
        Bs[koff + 2][row] = b.z; Bs[koff + 3][row] = b.w;
        __syncthreads();
#pragma unroll
        for (int kk = 0; kk < 8; kk++) {
            float ar[8], br[8];
            *(float4*)(ar)     = *(const float4*)&As[kk][ty * 8];
            *(float4*)(ar + 4) = *(const float4*)&As[kk][ty * 8 + 4];
            *(float4*)(br)     = *(const float4*)&Bs[kk][tx * 8];
            *(float4*)(br + 4) = *(const float4*)&Bs[kk][tx * 8 + 4];
#pragma unroll
            for (int i = 0; i < 8; i++)
#pragma unroll
                for (int j = 0; j < 8; j++)
                    acc[i][j] = fmaf(ar[i], br[j], acc[i][j]);
        }
    }
    // Epilogue: add tb (row term), capture diagonal, accuracy flags, staged store.
    float tbv[8];
#pragma unroll
    for (int i = 0; i < 8; i++) tbv[i] = g_tb[l * NN + ty * 8 + i];
#pragma unroll
    for (int i = 0; i < 8; i++)
#pragma unroll
        for (int j = 0; j < 8; j++) acc[i][j] += tbv[i];
    if (ty == tx) {
#pragma unroll
        for (int i = 0; i < 8; i++) pos[ty * 8 + i] = acc[i][i];
    }
    __syncthreads();
#pragma unroll
    for (int i = 0; i < 8; i++) {
        int n = ty * 8 + i;
        float pn = pos[n];
        bool ok = true;
#pragma unroll
        for (int j = 0; j < 8; j++) {
            int m = tx * 8 + j;
            ok = ok && ((m == n) || (pn > acc[i][j]));
        }
        flg[n][tx] = ok ? 1 : 0;
        size_t base = ((size_t)l * NN + n) * NN + tx * 8;
        *(float4*)&g_tmp[base] = make_float4(acc[i][0] * INV_T, acc[i][1] * INV_T,
                                             acc[i][2] * INV_T, acc[i][3] * INV_T);
        *(float4*)&g_tmp[base + 4] = make_float4(acc[i][4] * INV_T, acc[i][5] * INV_T,
                                                 acc[i][6] * INV_T, acc[i][7] * INV_T);
    }
    __syncthreads();
    if (tid < 128) {
        bool ok = true;
#pragma unroll
        for (int x = 0; x < 16; x++) ok = ok && (flg[tid][x] != 0);
        unsigned m = __ballot_sync(0xffffffffu, ok);
        if ((tid & 31) == 0) atomicAdd(&g_cnt[stepIdx], (unsigned)__popc(m));
    }
}

// g_tmp[l][n][m] -> out[n][m][kbase + l] (coalesced both sides via 32x32 smem tile)
__global__ void transpose_kernel(float* __restrict__ out, int Lp, int kbase) {
    __shared__ float tile[32][33];
    int n = blockIdx.z;
    int l0 = blockIdx.x * 32, m0 = blockIdx.y * 32;
    int tx = threadIdx.x, ty = threadIdx.y;
#pragma unroll
    for (int i = 0; i < 4; i++) {
        int l = l0 + ty + i * 8;
        if (l < Lp) tile[ty + i * 8][tx] = g_tmp[((size_t)l * NN + n) * NN + m0 + tx];
    }
    __syncthreads();
#pragma unroll
    for (int i = 0; i < 4; i++) {
        int m = m0 + ty + i * 8;
        int l = l0 + tx;
        if (l < Lp) out[((size_t)n * NN + m) * KTOT + kbase + l] = tile[tx][ty + i * 8];
    }
}

__global__ void ytrue_kernel(float* __restrict__ out) {
    int idx = blockIdx.x * 256 + threadIdx.x;
    if (idx < NN * KTOT) out[(size_t)NN * NN * KTOT + idx] = (float)(idx / KTOT);
}

__global__ void acc_kernel(float* __restrict__ out) {
    size_t off = (size_t)NN * NN * KTOT + (size_t)NN * KTOT;
    out[off + 0] = (float)g_cnt[0] / (float)(NN * L1S);
    out[off + 1] = (float)g_cnt[1] / (float)(NN * L2S);
}

extern "C" void kernel_launch(void* const* d_in, const int* in_sizes, int n_in,
                              void* d_out, int out_size) {
    const float* ts  = (const float*)d_in[0];
    const float* pts = (const float*)d_in[1];
    const float* W1  = (const float*)d_in[2];
    const float* b1  = (const float*)d_in[3];
    const float* W2  = (const float*)d_in[4];
    const float* b2  = (const float*)d_in[5];
    float* out = (float*)d_out;

    init_kernel<<<1, 1>>>();
    const float* Ws[2] = {W1, W2};
    const float* bs[2] = {b1, b2};
    int kb = 0;
    for (int si = 0; si < 2; si++) {
        int step = si + 1;
        int Lp = LFULL - step;
        tb_kernel<<<Lp, 128>>>(ts, bs[si], Lp, step);
        gemmU_kernel<<<dim3(4, Lp), 256>>>(ts, Ws[si], Lp, step);
        gemmL_kernel<<<Lp, 256>>>(pts, Lp, si);
        transpose_kernel<<<dim3(32, 4, 128), dim3(32, 8)>>>(out, Lp, kb);
        kb += Lp;
    }
    ytrue_kernel<<<(NN * KTOT + 255) / 256, 256>>>(out);
    acc_kernel<<<1, 1>>>(out);
}